// round 1
// baseline (speedup 1.0000x reference)
#include <cuda_runtime.h>
#include <math.h>

#define C_TOT 768
#define HH 180
#define WW 360
#define WF 91          // kept modes along W (of 181)
#define NPOS (HH*WF)   // 16380 positions per channel
#define NBLK 8
#define BS 96
#define PT 30          // MLP position tile (16380 = 546*30)

// (cos, sin)(2*pi*j/360)
__device__ float2 d_tw[360];
// scratch spectrum, layout [c][kh][wf<91], complex. Reused in-place by all stages.
__device__ float2 d_freq[(size_t)C_TOT * NPOS];

__global__ void k_init_tw() {
    int j = blockIdx.x * blockDim.x + threadIdx.x;
    if (j < 360) {
        double a = (2.0 * 3.14159265358979323846 / 360.0) * (double)j;
        d_tw[j] = make_float2((float)cos(a), (float)sin(a));
    }
}

// ---------------------------------------------------------------------------
// Kernel A: rfft along W (360 real -> 91 complex modes), one row per block.
// Two-step CT: N=360=18*20, n = 20*n1 + n2, k = k1 + 18*k2.
//   A[k1,n2] = sum_{n1<18} x[20 n1 + n2] e^{-2pi i n1 k1 / 18}
//   X[k]     = sum_{n2<20} A[k mod 18, n2] e^{-2pi i n2 k / 360}
// ---------------------------------------------------------------------------
__global__ __launch_bounds__(128) void k_fwd_w(const float* __restrict__ x) {
    __shared__ float  xs[360];
    __shared__ float2 As[360];
    __shared__ float2 tws[360];   // e^{-i theta}: (cos, -sin)
    int tid = threadIdx.x;
    int row = blockIdx.x;                       // c*180 + h
    const float* xr = x + (size_t)row * WW;
    for (int j = tid; j < 360; j += 128) {
        float2 w = d_tw[j];
        tws[j] = make_float2(w.x, -w.y);
        xs[j]  = xr[j];
    }
    __syncthreads();
    for (int idx = tid; idx < 360; idx += 128) {
        int k1 = idx / 20, n2 = idx % 20;
        float re = 0.f, im = 0.f;
        int t = 0, step = k1 * 20;              // ((n1*k1)%18)*20
        #pragma unroll
        for (int n1 = 0; n1 < 18; n1++) {
            float v = xs[20 * n1 + n2];
            float2 w = tws[t];
            re += v * w.x;
            im += v * w.y;
            t += step; if (t >= 360) t -= 360;
        }
        As[idx] = make_float2(re, im);
    }
    __syncthreads();
    float2* outp = d_freq + (size_t)row * WF;
    for (int k = tid; k < WF; k += 128) {
        int k1 = k % 18;
        float re = 0.f, im = 0.f;
        int t = 0;
        #pragma unroll
        for (int n2 = 0; n2 < 20; n2++) {
            float2 a = As[k1 * 20 + n2];
            float2 w = tws[t];
            re += a.x * w.x - a.y * w.y;
            im += a.x * w.y + a.y * w.x;
            t += k; if (t >= 360) t -= 360;
        }
        outp[k] = make_float2(re, im);
    }
}

// ---------------------------------------------------------------------------
// Kernel B/D: complex FFT of length 180 along kh, in-place on d_freq,
// 13 wf-columns per block (91 = 7*13). sgn=-1: forward, sgn=+1: inverse.
// N=180=12*15, n = 15*n1 + n2, k = k1 + 12*k2.
// ---------------------------------------------------------------------------
__global__ __launch_bounds__(256) void k_fft_h(float sgn, float scale) {
    __shared__ float2 in_s[180 * 13];
    __shared__ float2 A_s [180 * 13];
    __shared__ float2 tws[360];
    int tid = threadIdx.x;
    int c   = blockIdx.y;
    int wf0 = blockIdx.x * 13;
    float2* base = d_freq + (size_t)c * NPOS;
    for (int j = tid; j < 360; j += 256) {
        float2 w = d_tw[j];
        tws[j] = make_float2(w.x, sgn * w.y);   // e^{sgn * i theta}
    }
    for (int idx = tid; idx < 180 * 13; idx += 256) {
        int kh = idx / 13, col = idx % 13;
        in_s[idx] = base[(size_t)kh * WF + wf0 + col];
    }
    __syncthreads();
    // stage 1: A[(k1*15+n2)*13+col] = sum_{n1<12} in[(15 n1 + n2)*13+col] * e^{sgn i 2pi n1 k1/12}
    for (int idx = tid; idx < 180 * 13; idx += 256) {
        int j = idx / 13, col = idx % 13;
        int k1 = j / 15, n2 = j % 15;
        float re = 0.f, im = 0.f;
        int t = 0, step = k1 * 30;              // ((n1*k1)%12)*30
        #pragma unroll
        for (int n1 = 0; n1 < 12; n1++) {
            float2 a = in_s[(15 * n1 + n2) * 13 + col];
            float2 w = tws[t];
            re += a.x * w.x - a.y * w.y;
            im += a.x * w.y + a.y * w.x;
            t += step; if (t >= 360) t -= 360;
        }
        A_s[idx] = make_float2(re, im);
    }
    __syncthreads();
    // stage 2: X[k] = sum_{n2<15} A[(k%12)*15+n2] * e^{sgn i 2pi n2 k/180}
    for (int idx = tid; idx < 180 * 13; idx += 256) {
        int k = idx / 13, col = idx % 13;
        int k1 = k % 12;
        float re = 0.f, im = 0.f;
        int t = 0, step = 2 * k;                // (2*n2*k)%360 into 360-table
        #pragma unroll
        for (int n2 = 0; n2 < 15; n2++) {
            float2 a = A_s[(k1 * 15 + n2) * 13 + col];
            float2 w = tws[t];
            re += a.x * w.x - a.y * w.y;
            im += a.x * w.y + a.y * w.x;
            t += step; if (t >= 360) t -= 360;
        }
        base[(size_t)k * WF + wf0 + col] = make_float2(re * scale, im * scale);
    }
}

// ---------------------------------------------------------------------------
// Kernel C: block-diagonal complex MLP + softshrink, in-place on d_freq.
// Block = (p-tile of 30 positions, channel-block k). 288 threads:
// thread = (o in [0,96), pg in [0,3)), each accumulates 10 positions.
// ---------------------------------------------------------------------------
__global__ __launch_bounds__(288) void k_mlp(const float* __restrict__ w1,
                                             const float* __restrict__ b1,
                                             const float* __restrict__ w2,
                                             const float* __restrict__ b2) {
    __shared__ float2 a_s [BS * PT];
    __shared__ float2 o1_s[BS * PT];
    int tid = threadIdx.x;
    int k   = blockIdx.y;
    int p0  = blockIdx.x * PT;

    for (int idx = tid; idx < BS * PT; idx += 288) {
        int i = idx / PT, pp = idx % PT;
        a_s[idx] = d_freq[(size_t)(k * BS + i) * NPOS + p0 + pp];
    }
    __syncthreads();

    int o  = tid % 96;
    int pg = tid / 96;   // 0..2
    const float2* W1 = (const float2*)w1 + (size_t)k * BS * BS;
    const float2* W2 = (const float2*)w2 + (size_t)k * BS * BS;
    const float2  Bb1 = ((const float2*)b1)[k * BS + o];
    const float2  Bb2 = ((const float2*)b2)[k * BS + o];

    float accr[10], acci[10];
    #pragma unroll
    for (int p = 0; p < 10; p++) { accr[p] = Bb1.x; acci[p] = Bb1.y; }
    for (int i = 0; i < 96; i++) {
        float2 w = W1[i * 96 + o];
        #pragma unroll
        for (int p = 0; p < 10; p++) {
            float2 a = a_s[i * PT + pg * 10 + p];
            accr[p] += a.x * w.x - a.y * w.y;
            acci[p] += a.x * w.y + a.y * w.x;
        }
    }
    #pragma unroll
    for (int p = 0; p < 10; p++)
        o1_s[o * PT + pg * 10 + p] = make_float2(fmaxf(accr[p], 0.f),
                                                 fmaxf(acci[p], 0.f));
    __syncthreads();

    #pragma unroll
    for (int p = 0; p < 10; p++) { accr[p] = Bb2.x; acci[p] = Bb2.y; }
    for (int i = 0; i < 96; i++) {
        float2 w = W2[i * 96 + o];
        #pragma unroll
        for (int p = 0; p < 10; p++) {
            float2 a = o1_s[i * PT + pg * 10 + p];
            accr[p] += a.x * w.x - a.y * w.y;
            acci[p] += a.x * w.y + a.y * w.x;
        }
    }
    // softshrink(0.01), write to a_s (no longer read)
    #pragma unroll
    for (int p = 0; p < 10; p++) {
        float r = accr[p], m = acci[p];
        float vr = fabsf(r) - 0.01f;
        float vi = fabsf(m) - 0.01f;
        r = vr > 0.f ? copysignf(vr, r) : 0.f;
        m = vi > 0.f ? copysignf(vi, m) : 0.f;
        a_s[o * PT + pg * 10 + p] = make_float2(r, m);
    }
    __syncthreads();
    for (int idx = tid; idx < BS * PT; idx += 288) {
        int i = idx / PT, pp = idx % PT;
        d_freq[(size_t)(k * BS + i) * NPOS + p0 + pp] = a_s[idx];
    }
}

// ---------------------------------------------------------------------------
// Kernel E: irfft along W (91 half-spectrum modes -> 360 reals) + residual.
// Build hermitian-extended Xfull[360] in smem, two-step CT inverse:
//   T[w1,k2] = sum_{k1<18} Xf[k2 + 20 k1] e^{+2pi i w1 k1/18}
//   x[w]     = Re sum_{k2<20} T[w mod 18, k2] e^{+2pi i k2 w/360}
// ---------------------------------------------------------------------------
__global__ __launch_bounds__(128) void k_inv_w(const float* __restrict__ xin,
                                               float* __restrict__ outp) {
    __shared__ float2 Xf[360];
    __shared__ float2 T [360];
    __shared__ float2 tws[360];   // e^{+i theta}
    int tid = threadIdx.x;
    int row = blockIdx.x;                        // c*180 + h
    const float2* g = d_freq + (size_t)row * WF;
    for (int j = tid; j < 360; j += 128) tws[j] = d_tw[j];
    for (int j = tid; j < 360; j += 128) {
        float2 v;
        if (j <= 90)        v = g[j];
        else if (j >= 270) { float2 u = g[360 - j]; v = make_float2(u.x, -u.y); }
        else                v = make_float2(0.f, 0.f);
        Xf[j] = v;
    }
    __syncthreads();
    for (int idx = tid; idx < 360; idx += 128) {
        int w1 = idx / 20, k2 = idx % 20;
        float re = 0.f, im = 0.f;
        int t = 0, step = w1 * 20;
        #pragma unroll
        for (int k1 = 0; k1 < 18; k1++) {
            float2 a = Xf[k2 + 20 * k1];
            float2 w = tws[t];
            re += a.x * w.x - a.y * w.y;
            im += a.x * w.y + a.y * w.x;
            t += step; if (t >= 360) t -= 360;
        }
        T[idx] = make_float2(re, im);
    }
    __syncthreads();
    const float s = 3.9283710065919305e-3f;      // 1/sqrt(180*360)
    const float* xr = xin  + (size_t)row * WW;
    float*       orw = outp + (size_t)row * WW;
    for (int w = tid; w < 360; w += 128) {
        int w1 = w % 18;
        float acc = 0.f;
        int t = 0, step = w;
        #pragma unroll
        for (int k2 = 0; k2 < 20; k2++) {
            float2 a  = T[w1 * 20 + k2];
            float2 tw = tws[t];
            acc += a.x * tw.x - a.y * tw.y;      // real part
            t += step; if (t >= 360) t -= 360;
        }
        orw[w] = xr[w] + s * acc;
    }
}

// ---------------------------------------------------------------------------
extern "C" void kernel_launch(void* const* d_in, const int* in_sizes, int n_in,
                              void* d_out, int out_size) {
    const float* x  = (const float*)d_in[0];
    const float* w1 = (const float*)d_in[1];
    const float* b1 = (const float*)d_in[2];
    const float* w2 = (const float*)d_in[3];
    const float* b2 = (const float*)d_in[4];
    float* out = (float*)d_out;

    const float s_fwd = 3.9283710065919305e-3f;  // 1/sqrt(64800), ortho fwd

    k_init_tw<<<3, 128>>>();
    k_fwd_w<<<C_TOT * HH, 128>>>(x);
    k_fft_h<<<dim3(7, C_TOT), 256>>>(-1.f, s_fwd);   // forward H FFT + ortho norm
    k_mlp  <<<dim3(NPOS / PT, NBLK), 288>>>(w1, b1, w2, b2);
    k_fft_h<<<dim3(7, C_TOT), 256>>>( 1.f, 1.f);     // inverse H FFT
    k_inv_w<<<C_TOT * HH, 128>>>(x, out);
}

// round 2
// speedup vs baseline: 1.3112x; 1.3112x over previous
#include <cuda_runtime.h>
#include <math.h>

#define C_TOT 768
#define HH 180
#define WW 360
#define WF 91          // kept modes along W (of 181)
#define NPOS (HH*WF)   // 16380 positions per channel
#define NBLK 8
#define BS 96
#define PT 30          // MLP position tile (16380 = 546*30)
#define RB 4           // rows batched per block in W kernels

// (cos, sin)(2*pi*j/360)
__device__ float2 d_tw[360];
// scratch spectrum, layout [c][kh][wf<91], complex. Reused in-place by all stages.
__device__ float2 d_freq[(size_t)C_TOT * NPOS];

__global__ void k_init_tw() {
    int j = blockIdx.x * blockDim.x + threadIdx.x;
    if (j < 360) {
        double a = (2.0 * 3.14159265358979323846 / 360.0) * (double)j;
        d_tw[j] = make_float2((float)cos(a), (float)sin(a));
    }
}

// ---------------------------------------------------------------------------
// Kernel A: rfft along W (360 real -> 91 complex), RB=4 rows per block.
// Two-step CT: N=360=18*20, n = 20*n1 + n2, k = k1 + 18*k2.
// Row-interleaved smem planes [j][4] so one LDS.128 feeds 4 rows.
// ---------------------------------------------------------------------------
__global__ __launch_bounds__(128) void k_fwd_w(const float* __restrict__ x) {
    __shared__ __align__(16) float xs [360 * RB];
    __shared__ __align__(16) float Asr[360 * RB];
    __shared__ __align__(16) float Asi[360 * RB];
    __shared__ float2 tws[360];   // e^{-i theta}
    int tid  = threadIdx.x;
    int row0 = blockIdx.x * RB;
    const float* xr = x + (size_t)row0 * WW;
    for (int j = tid; j < 360; j += 128) {
        float2 w = d_tw[j];
        tws[j] = make_float2(w.x, -w.y);
    }
    for (int idx = tid; idx < 360 * RB; idx += 128) {
        int r = idx / 360, j = idx % 360;
        xs[j * RB + r] = xr[idx];               // xr[r*360 + j], coalesced
    }
    __syncthreads();
    // stage 1: A[k1,n2] per 4 rows
    for (int idx = tid; idx < 360; idx += 128) {
        int k1 = idx / 20, n2 = idx % 20;
        float ar0=0,ar1=0,ar2=0,ar3=0, ai0=0,ai1=0,ai2=0,ai3=0;
        int t = 0, step = k1 * 20;
        #pragma unroll
        for (int n1 = 0; n1 < 18; n1++) {
            float4 v = *(const float4*)&xs[(20 * n1 + n2) * RB];
            float2 w = tws[t];
            ar0 += v.x * w.x; ai0 += v.x * w.y;
            ar1 += v.y * w.x; ai1 += v.y * w.y;
            ar2 += v.z * w.x; ai2 += v.z * w.y;
            ar3 += v.w * w.x; ai3 += v.w * w.y;
            t += step; if (t >= 360) t -= 360;
        }
        *(float4*)&Asr[idx * RB] = make_float4(ar0, ar1, ar2, ar3);
        *(float4*)&Asi[idx * RB] = make_float4(ai0, ai1, ai2, ai3);
    }
    __syncthreads();
    // stage 2: X[k] = sum_{n2<20} A[k%18, n2] e^{-2pi i n2 k/360}
    for (int k = tid; k < WF; k += 128) {
        int k1 = k % 18;
        float rr0=0,rr1=0,rr2=0,rr3=0, ii0=0,ii1=0,ii2=0,ii3=0;
        int t = 0;
        #pragma unroll
        for (int n2 = 0; n2 < 20; n2++) {
            float4 ar = *(const float4*)&Asr[(k1 * 20 + n2) * RB];
            float4 ai = *(const float4*)&Asi[(k1 * 20 + n2) * RB];
            float2 w = tws[t];
            rr0 += ar.x * w.x - ai.x * w.y;  ii0 += ar.x * w.y + ai.x * w.x;
            rr1 += ar.y * w.x - ai.y * w.y;  ii1 += ar.y * w.y + ai.y * w.x;
            rr2 += ar.z * w.x - ai.z * w.y;  ii2 += ar.z * w.y + ai.z * w.x;
            rr3 += ar.w * w.x - ai.w * w.y;  ii3 += ar.w * w.y + ai.w * w.x;
            t += k; if (t >= 360) t -= 360;
        }
        d_freq[(size_t)(row0 + 0) * WF + k] = make_float2(rr0, ii0);
        d_freq[(size_t)(row0 + 1) * WF + k] = make_float2(rr1, ii1);
        d_freq[(size_t)(row0 + 2) * WF + k] = make_float2(rr2, ii2);
        d_freq[(size_t)(row0 + 3) * WF + k] = make_float2(rr3, ii3);
    }
}

// ---------------------------------------------------------------------------
// Kernel B/D: complex FFT length 180 along kh, 13 wf-columns per block.
// Each thread owns one j/k index and ALL 13 columns in registers, so one
// twiddle load amortizes over 52 FMA. Planes transposed [col][kh] for
// conflict-free scalar LDS. sgn=-1 fwd, +1 inv. N=180=12*15.
// ---------------------------------------------------------------------------
__global__ __launch_bounds__(192) void k_fft_h(float sgn, float scale) {
    __shared__ float inr[13 * 180], ini[13 * 180];
    __shared__ float Ar [13 * 180], Ai [13 * 180];
    __shared__ float2 tws[360];
    int tid = threadIdx.x;
    int c   = blockIdx.y;
    int wf0 = blockIdx.x * 13;
    float2* base = d_freq + (size_t)c * NPOS;
    for (int j = tid; j < 360; j += 192) {
        float2 w = d_tw[j];
        tws[j] = make_float2(w.x, sgn * w.y);
    }
    for (int idx = tid; idx < 180 * 13; idx += 192) {
        int kh = idx / 13, col = idx % 13;
        float2 v = base[(size_t)kh * WF + wf0 + col];
        inr[col * 180 + kh] = v.x;
        ini[col * 180 + kh] = v.y;
    }
    __syncthreads();
    // stage 1: A[k1*15+n2] = sum_{n1<12} in[15 n1 + n2] * e^{sgn i 2pi n1 k1/12}
    if (tid < 180) {
        int k1 = tid / 15, n2 = tid % 15;
        float ar[13], ai[13];
        #pragma unroll
        for (int cc = 0; cc < 13; cc++) { ar[cc] = 0.f; ai[cc] = 0.f; }
        int t = 0, step = k1 * 30;
        #pragma unroll
        for (int n1 = 0; n1 < 12; n1++) {
            int src = 15 * n1 + n2;
            float2 w = tws[t];
            #pragma unroll
            for (int cc = 0; cc < 13; cc++) {
                float xr = inr[cc * 180 + src];
                float xi = ini[cc * 180 + src];
                ar[cc] += xr * w.x - xi * w.y;
                ai[cc] += xr * w.y + xi * w.x;
            }
            t += step; if (t >= 360) t -= 360;
        }
        #pragma unroll
        for (int cc = 0; cc < 13; cc++) {
            Ar[cc * 180 + tid] = ar[cc];
            Ai[cc * 180 + tid] = ai[cc];
        }
    }
    __syncthreads();
    // stage 2: X[k] = sum_{n2<15} A[(k%12)*15+n2] * e^{sgn i 2pi n2 k/180}
    if (tid < 180) {
        int k = tid, k1 = k % 12;
        float rr[13], ii[13];
        #pragma unroll
        for (int cc = 0; cc < 13; cc++) { rr[cc] = 0.f; ii[cc] = 0.f; }
        int t = 0, step = 2 * k;
        #pragma unroll
        for (int n2 = 0; n2 < 15; n2++) {
            int src = k1 * 15 + n2;
            float2 w = tws[t];
            #pragma unroll
            for (int cc = 0; cc < 13; cc++) {
                float xr = Ar[cc * 180 + src];
                float xi = Ai[cc * 180 + src];
                rr[cc] += xr * w.x - xi * w.y;
                ii[cc] += xr * w.y + xi * w.x;
            }
            t += step; if (t >= 360) t -= 360;
        }
        float2* ob = base + (size_t)k * WF + wf0;
        #pragma unroll
        for (int cc = 0; cc < 13; cc++)
            ob[cc] = make_float2(rr[cc] * scale, ii[cc] * scale);
    }
}

// ---------------------------------------------------------------------------
// Kernel C: block-diagonal complex MLP + softshrink, in-place on d_freq.
// ---------------------------------------------------------------------------
__global__ __launch_bounds__(288) void k_mlp(const float* __restrict__ w1,
                                             const float* __restrict__ b1,
                                             const float* __restrict__ w2,
                                             const float* __restrict__ b2) {
    __shared__ float2 a_s [BS * PT];
    __shared__ float2 o1_s[BS * PT];
    int tid = threadIdx.x;
    int k   = blockIdx.y;
    int p0  = blockIdx.x * PT;

    for (int idx = tid; idx < BS * PT; idx += 288) {
        int i = idx / PT, pp = idx % PT;
        a_s[idx] = d_freq[(size_t)(k * BS + i) * NPOS + p0 + pp];
    }
    __syncthreads();

    int o  = tid % 96;
    int pg = tid / 96;   // 0..2
    const float2* W1 = (const float2*)w1 + (size_t)k * BS * BS;
    const float2* W2 = (const float2*)w2 + (size_t)k * BS * BS;
    const float2  Bb1 = ((const float2*)b1)[k * BS + o];
    const float2  Bb2 = ((const float2*)b2)[k * BS + o];

    float accr[10], acci[10];
    #pragma unroll
    for (int p = 0; p < 10; p++) { accr[p] = Bb1.x; acci[p] = Bb1.y; }
    for (int i = 0; i < 96; i++) {
        float2 w = W1[i * 96 + o];
        #pragma unroll
        for (int p = 0; p < 10; p++) {
            float2 a = a_s[i * PT + pg * 10 + p];
            accr[p] += a.x * w.x - a.y * w.y;
            acci[p] += a.x * w.y + a.y * w.x;
        }
    }
    #pragma unroll
    for (int p = 0; p < 10; p++)
        o1_s[o * PT + pg * 10 + p] = make_float2(fmaxf(accr[p], 0.f),
                                                 fmaxf(acci[p], 0.f));
    __syncthreads();

    #pragma unroll
    for (int p = 0; p < 10; p++) { accr[p] = Bb2.x; acci[p] = Bb2.y; }
    for (int i = 0; i < 96; i++) {
        float2 w = W2[i * 96 + o];
        #pragma unroll
        for (int p = 0; p < 10; p++) {
            float2 a = o1_s[i * PT + pg * 10 + p];
            accr[p] += a.x * w.x - a.y * w.y;
            acci[p] += a.x * w.y + a.y * w.x;
        }
    }
    #pragma unroll
    for (int p = 0; p < 10; p++) {
        float r = accr[p], m = acci[p];
        float vr = fabsf(r) - 0.01f;
        float vi = fabsf(m) - 0.01f;
        r = vr > 0.f ? copysignf(vr, r) : 0.f;
        m = vi > 0.f ? copysignf(vi, m) : 0.f;
        a_s[o * PT + pg * 10 + p] = make_float2(r, m);
    }
    __syncthreads();
    for (int idx = tid; idx < BS * PT; idx += 288) {
        int i = idx / PT, pp = idx % PT;
        d_freq[(size_t)(k * BS + i) * NPOS + p0 + pp] = a_s[idx];
    }
}

// ---------------------------------------------------------------------------
// Kernel E: irfft along W (91 modes -> 360 reals) + residual, RB=4 rows/block.
// Hermitian-extend to Xf[360] planes, two-step CT inverse.
// ---------------------------------------------------------------------------
__global__ __launch_bounds__(128) void k_inv_w(const float* __restrict__ xin,
                                               float* __restrict__ outp) {
    __shared__ __align__(16) float Xfr[360 * RB], Xfi[360 * RB];
    __shared__ __align__(16) float Tr [360 * RB], Ti [360 * RB];
    __shared__ float2 tws[360];   // e^{+i theta}
    int tid  = threadIdx.x;
    int row0 = blockIdx.x * RB;
    for (int j = tid; j < 360; j += 128) tws[j] = d_tw[j];
    for (int idx = tid; idx < 360 * RB; idx += 128) {
        int r = idx / 360, j = idx % 360;
        const float2* g = d_freq + (size_t)(row0 + r) * WF;
        float2 v;
        if (j <= 90)        v = g[j];
        else if (j >= 270) { float2 u = g[360 - j]; v = make_float2(u.x, -u.y); }
        else                v = make_float2(0.f, 0.f);
        Xfr[j * RB + r] = v.x;
        Xfi[j * RB + r] = v.y;
    }
    __syncthreads();
    // stage 1: T[w1,k2] = sum_{k1<18} Xf[k2+20 k1] e^{+2pi i w1 k1/18}
    for (int idx = tid; idx < 360; idx += 128) {
        int w1 = idx / 20, k2 = idx % 20;
        float rr0=0,rr1=0,rr2=0,rr3=0, ii0=0,ii1=0,ii2=0,ii3=0;
        int t = 0, step = w1 * 20;
        #pragma unroll
        for (int k1 = 0; k1 < 18; k1++) {
            float4 xr = *(const float4*)&Xfr[(k2 + 20 * k1) * RB];
            float4 xi = *(const float4*)&Xfi[(k2 + 20 * k1) * RB];
            float2 w = tws[t];
            rr0 += xr.x * w.x - xi.x * w.y;  ii0 += xr.x * w.y + xi.x * w.x;
            rr1 += xr.y * w.x - xi.y * w.y;  ii1 += xr.y * w.y + xi.y * w.x;
            rr2 += xr.z * w.x - xi.z * w.y;  ii2 += xr.z * w.y + xi.z * w.x;
            rr3 += xr.w * w.x - xi.w * w.y;  ii3 += xr.w * w.y + xi.w * w.x;
            t += step; if (t >= 360) t -= 360;
        }
        *(float4*)&Tr[idx * RB] = make_float4(rr0, rr1, rr2, rr3);
        *(float4*)&Ti[idx * RB] = make_float4(ii0, ii1, ii2, ii3);
    }
    __syncthreads();
    // stage 2: x[w] = Re sum_{k2<20} T[w%18, k2] e^{+2pi i k2 w/360}
    const float s = 3.9283710065919305e-3f;      // 1/sqrt(180*360)
    for (int w = tid; w < 360; w += 128) {
        int w1 = w % 18;
        float a0=0,a1=0,a2=0,a3=0;
        int t = 0;
        #pragma unroll
        for (int k2 = 0; k2 < 20; k2++) {
            float4 ar = *(const float4*)&Tr[(w1 * 20 + k2) * RB];
            float4 ai = *(const float4*)&Ti[(w1 * 20 + k2) * RB];
            float2 tw = tws[t];
            a0 += ar.x * tw.x - ai.x * tw.y;
            a1 += ar.y * tw.x - ai.y * tw.y;
            a2 += ar.z * tw.x - ai.z * tw.y;
            a3 += ar.w * tw.x - ai.w * tw.y;
            t += w; if (t >= 360) t -= 360;
        }
        outp[(size_t)(row0 + 0) * WW + w] = xin[(size_t)(row0 + 0) * WW + w] + s * a0;
        outp[(size_t)(row0 + 1) * WW + w] = xin[(size_t)(row0 + 1) * WW + w] + s * a1;
        outp[(size_t)(row0 + 2) * WW + w] = xin[(size_t)(row0 + 2) * WW + w] + s * a2;
        outp[(size_t)(row0 + 3) * WW + w] = xin[(size_t)(row0 + 3) * WW + w] + s * a3;
    }
}

// ---------------------------------------------------------------------------
extern "C" void kernel_launch(void* const* d_in, const int* in_sizes, int n_in,
                              void* d_out, int out_size) {
    const float* x  = (const float*)d_in[0];
    const float* w1 = (const float*)d_in[1];
    const float* b1 = (const float*)d_in[2];
    const float* w2 = (const float*)d_in[3];
    const float* b2 = (const float*)d_in[4];
    float* out = (float*)d_out;

    const float s_fwd = 3.9283710065919305e-3f;  // 1/sqrt(64800), ortho fwd

    k_init_tw<<<3, 128>>>();
    k_fwd_w<<<C_TOT * HH / RB, 128>>>(x);
    k_fft_h<<<dim3(7, C_TOT), 192>>>(-1.f, s_fwd);   // forward H FFT + ortho norm
    k_mlp  <<<dim3(NPOS / PT, NBLK), 288>>>(w1, b1, w2, b2);
    k_fft_h<<<dim3(7, C_TOT), 192>>>( 1.f, 1.f);     // inverse H FFT
    k_inv_w<<<C_TOT * HH / RB, 128>>>(x, out);
}

// round 4
// speedup vs baseline: 2.2100x; 1.6855x over previous
#include <cuda_runtime.h>
#include <math.h>

#define C_TOT 768
#define HH 180
#define WW 360
#define WF 91          // kept modes along W (of 181)
#define NPOS (HH*WF)   // 16380 positions per channel
#define NBLK 8
#define BS 96
#define PT 30          // MLP position tile
#define RB6 6          // rows per block in W kernels

// (cos, sin)(2*pi*j/360)
__device__ float2 d_tw[360];
// scratch spectrum, layout [c][kh][wf<91], complex
__device__ float2 d_freq[(size_t)C_TOT * NPOS];

// compile-time root tables: CN[j]=cos(2pi j/N), SN[j]=sin(2pi j/N)
__device__ constexpr float C12T[12] = {1.f, 0.8660254f, 0.5f, 0.f, -0.5f, -0.8660254f,
                            -1.f, -0.8660254f, -0.5f, 0.f, 0.5f, 0.8660254f};
__device__ constexpr float S12T[12] = {0.f, 0.5f, 0.8660254f, 1.f, 0.8660254f, 0.5f,
                            0.f, -0.5f, -0.8660254f, -1.f, -0.8660254f, -0.5f};
__device__ constexpr float C15T[15] = {1.f, 0.91354546f, 0.66913061f, 0.30901699f, -0.10452846f,
                            -0.5f, -0.80901699f, -0.97814760f, -0.97814760f, -0.80901699f,
                            -0.5f, -0.10452846f, 0.30901699f, 0.66913061f, 0.91354546f};
__device__ constexpr float S15T[15] = {0.f, 0.40673664f, 0.74314483f, 0.95105652f, 0.99452190f,
                            0.86602540f, 0.58778525f, 0.20791169f, -0.20791169f, -0.58778525f,
                            -0.86602540f, -0.99452190f, -0.95105652f, -0.74314483f, -0.40673664f};
__device__ constexpr float C18T[18] = {1.f, 0.93969262f, 0.76604444f, 0.5f, 0.17364818f, -0.17364818f,
                            -0.5f, -0.76604444f, -0.93969262f, -1.f, -0.93969262f, -0.76604444f,
                            -0.5f, -0.17364818f, 0.17364818f, 0.5f, 0.76604444f, 0.93969262f};
__device__ constexpr float S18T[18] = {0.f, 0.34202014f, 0.64278761f, 0.86602540f, 0.98480775f, 0.98480775f,
                            0.86602540f, 0.64278761f, 0.34202014f, 0.f, -0.34202014f, -0.64278761f,
                            -0.86602540f, -0.98480775f, -0.98480775f, -0.86602540f, -0.64278761f, -0.34202014f};
__device__ constexpr float C20T[20] = {1.f, 0.95105652f, 0.80901699f, 0.58778525f, 0.30901699f, 0.f,
                            -0.30901699f, -0.58778525f, -0.80901699f, -0.95105652f, -1.f,
                            -0.95105652f, -0.80901699f, -0.58778525f, -0.30901699f, 0.f,
                            0.30901699f, 0.58778525f, 0.80901699f, 0.95105652f};
__device__ constexpr float S20T[20] = {0.f, 0.30901699f, 0.58778525f, 0.80901699f, 0.95105652f, 1.f,
                            0.95105652f, 0.80901699f, 0.58778525f, 0.30901699f, 0.f,
                            -0.30901699f, -0.58778525f, -0.80901699f, -0.95105652f, -1.f,
                            -0.95105652f, -0.80901699f, -0.58778525f, -0.30901699f};

__global__ void k_init_tw() {
    int j = blockIdx.x * blockDim.x + threadIdx.x;
    if (j < 360) {
        double a = (2.0 * 3.14159265358979323846 / 360.0) * (double)j;
        d_tw[j] = make_float2((float)cos(a), (float)sin(a));
    }
}

// ---------------------------------------------------------------------------
// Kernel A: rfft along W. 360 = 18*20, n = 18*n1 + n2, k = km + 20*k2 (k<91).
// stage1: per-thread real DFT-20 (hermitian), constant twiddles.
// stage2: pre-twiddle by e^{-2pi i n2 km/360} (table) + register DFT-18.
// ---------------------------------------------------------------------------
__global__ __launch_bounds__(128) void k_fwd_w(const float* __restrict__ x) {
    __shared__ float  xs[RB6][WW];
    __shared__ float2 As[20][18][RB6];   // [km][n2][r]
    __shared__ float2 tws[360];          // e^{-i theta}
    int tid = threadIdx.x;
    size_t row0 = (size_t)blockIdx.x * RB6;
    for (int j = tid; j < 360; j += 128) {
        float2 w = d_tw[j];
        tws[j] = make_float2(w.x, -w.y);
    }
    for (int idx = tid; idx < RB6 * WW; idx += 128)
        xs[idx / WW][idx % WW] = x[row0 * WW + idx];
    __syncthreads();
    if (tid < 18 * RB6) {
        int n2 = tid % 18, r = tid / 18;
        float v[20];
        #pragma unroll
        for (int n1 = 0; n1 < 20; n1++) v[n1] = xs[r][18 * n1 + n2];
        #pragma unroll
        for (int km = 0; km <= 10; km++) {
            float re = 0.f, im = 0.f;
            #pragma unroll
            for (int n1 = 0; n1 < 20; n1++) {
                int m = (n1 * km) % 20;
                re += v[n1] * C20T[m];
                im -= v[n1] * S20T[m];
            }
            As[km][n2][r] = make_float2(re, im);
            if (km >= 1 && km <= 9) As[20 - km][n2][r] = make_float2(re, -im);
        }
    }
    __syncthreads();
    if (tid < 20 * RB6) {
        int km = tid % 20, r = tid / 20;
        float2 B[18];
        int t = 0;
        #pragma unroll
        for (int n2 = 0; n2 < 18; n2++) {
            float2 a = As[km][n2][r];
            float2 w = tws[t];                   // e^{-2pi i n2 km/360}
            B[n2] = make_float2(a.x * w.x - a.y * w.y, a.x * w.y + a.y * w.x);
            t += km; if (t >= 360) t -= 360;
        }
        float2* orow = d_freq + (row0 + r) * WF;
        #pragma unroll
        for (int k2 = 0; k2 < 5; k2++) {
            int k = km + 20 * k2;
            if (k < WF) {
                float xr = 0.f, xi = 0.f;
                #pragma unroll
                for (int n2 = 0; n2 < 18; n2++) {
                    int m = (n2 * k2) % 18;      // e^{-2pi i n2 k2/18}
                    xr += B[n2].x * C18T[m] + B[n2].y * S18T[m];
                    xi += B[n2].y * C18T[m] - B[n2].x * S18T[m];
                }
                orow[k] = make_float2(xr, xi);
            }
        }
    }
}

// ---------------------------------------------------------------------------
// Kernel B/D: complex FFT length 180 along kh. 180 = 12*15, n = 15*n1+n2,
// k = km + 12*k2. stage1: register DFT-12; stage2: table pre-twiddle +
// register DFT-15. SGN=-1 fwd, +1 inv (compile-time).
// ---------------------------------------------------------------------------
template <int SGN>
__global__ __launch_bounds__(224) void k_fft_h(float scale) {
    __shared__ float2 in_s[13][HH];      // input [col][kh]; reused as output [col][k]
    __shared__ float2 As[13][12][15];    // [col][km][n2]
    __shared__ float2 tws[360];          // e^{SGN i theta}
    int tid = threadIdx.x;
    int c   = blockIdx.y;
    int wf0 = blockIdx.x * 13;
    float2* base = d_freq + (size_t)c * NPOS;
    for (int j = tid; j < 360; j += 224) {
        float2 w = d_tw[j];
        tws[j] = make_float2(w.x, SGN < 0 ? -w.y : w.y);
    }
    for (int idx = tid; idx < HH * 13; idx += 224) {
        int kh = idx / 13, col = idx % 13;
        in_s[col][kh] = base[(size_t)kh * WF + wf0 + col];
    }
    __syncthreads();
    if (tid < 15 * 13) {
        int n2 = tid % 15, col = tid / 15;
        float2 v[12];
        #pragma unroll
        for (int n1 = 0; n1 < 12; n1++) v[n1] = in_s[col][15 * n1 + n2];
        #pragma unroll
        for (int km = 0; km < 12; km++) {
            float ar = 0.f, ai = 0.f;
            #pragma unroll
            for (int n1 = 0; n1 < 12; n1++) {
                int m = (n1 * km) % 12;
                float cc = C12T[m];
                float ss = (SGN < 0) ? -S12T[m] : S12T[m];
                ar += v[n1].x * cc - v[n1].y * ss;
                ai += v[n1].x * ss + v[n1].y * cc;
            }
            As[col][km][n2] = make_float2(ar, ai);
        }
    }
    __syncthreads();
    if (tid < 12 * 13) {
        int km = tid % 12, col = tid / 12;
        float2 B[15];
        int t = 0, step = 2 * km;
        #pragma unroll
        for (int n2 = 0; n2 < 15; n2++) {
            float2 a = As[col][km][n2];
            float2 w = tws[t];                   // e^{SGN 2pi i n2 km/180}
            B[n2] = make_float2(a.x * w.x - a.y * w.y, a.x * w.y + a.y * w.x);
            t += step; if (t >= 360) t -= 360;
        }
        #pragma unroll
        for (int k2 = 0; k2 < 15; k2++) {
            float xr = 0.f, xi = 0.f;
            #pragma unroll
            for (int n2 = 0; n2 < 15; n2++) {
                int m = (n2 * k2) % 15;
                float cc = C15T[m];
                float ss = (SGN < 0) ? -S15T[m] : S15T[m];
                xr += B[n2].x * cc - B[n2].y * ss;
                xi += B[n2].x * ss + B[n2].y * cc;
            }
            in_s[col][km + 12 * k2] = make_float2(xr, xi);
        }
    }
    __syncthreads();
    for (int idx = tid; idx < HH * 13; idx += 224) {
        int k = idx / 13, col = idx % 13;
        float2 v = in_s[col][k];
        base[(size_t)k * WF + wf0 + col] = make_float2(v.x * scale, v.y * scale);
    }
}

// ---------------------------------------------------------------------------
// Kernel C: block-diagonal complex MLP + softshrink, in-place on d_freq.
// ---------------------------------------------------------------------------
__global__ __launch_bounds__(288) void k_mlp(const float* __restrict__ w1,
                                             const float* __restrict__ b1,
                                             const float* __restrict__ w2,
                                             const float* __restrict__ b2) {
    __shared__ float2 a_s [BS * PT];
    __shared__ float2 o1_s[BS * PT];
    int tid = threadIdx.x;
    int k   = blockIdx.y;
    int p0  = blockIdx.x * PT;

    for (int idx = tid; idx < BS * PT; idx += 288) {
        int i = idx / PT, pp = idx % PT;
        a_s[idx] = d_freq[(size_t)(k * BS + i) * NPOS + p0 + pp];
    }
    __syncthreads();

    int o  = tid % 96;
    int pg = tid / 96;
    const float2* W1 = (const float2*)w1 + (size_t)k * BS * BS;
    const float2* W2 = (const float2*)w2 + (size_t)k * BS * BS;
    const float2  Bb1 = ((const float2*)b1)[k * BS + o];
    const float2  Bb2 = ((const float2*)b2)[k * BS + o];

    float accr[10], acci[10];
    #pragma unroll
    for (int p = 0; p < 10; p++) { accr[p] = Bb1.x; acci[p] = Bb1.y; }
    for (int i = 0; i < 96; i++) {
        float2 w = W1[i * 96 + o];
        #pragma unroll
        for (int p = 0; p < 10; p++) {
            float2 a = a_s[i * PT + pg * 10 + p];
            accr[p] += a.x * w.x - a.y * w.y;
            acci[p] += a.x * w.y + a.y * w.x;
        }
    }
    #pragma unroll
    for (int p = 0; p < 10; p++)
        o1_s[o * PT + pg * 10 + p] = make_float2(fmaxf(accr[p], 0.f),
                                                 fmaxf(acci[p], 0.f));
    __syncthreads();

    #pragma unroll
    for (int p = 0; p < 10; p++) { accr[p] = Bb2.x; acci[p] = Bb2.y; }
    for (int i = 0; i < 96; i++) {
        float2 w = W2[i * 96 + o];
        #pragma unroll
        for (int p = 0; p < 10; p++) {
            float2 a = o1_s[i * PT + pg * 10 + p];
            accr[p] += a.x * w.x - a.y * w.y;
            acci[p] += a.x * w.y + a.y * w.x;
        }
    }
    #pragma unroll
    for (int p = 0; p < 10; p++) {
        float r = accr[p], m = acci[p];
        float vr = fabsf(r) - 0.01f;
        float vi = fabsf(m) - 0.01f;
        r = vr > 0.f ? copysignf(vr, r) : 0.f;
        m = vi > 0.f ? copysignf(vi, m) : 0.f;
        a_s[o * PT + pg * 10 + p] = make_float2(r, m);
    }
    __syncthreads();
    for (int idx = tid; idx < BS * PT; idx += 288) {
        int i = idx / PT, pp = idx % PT;
        d_freq[(size_t)(k * BS + i) * NPOS + p0 + pp] = a_s[idx];
    }
}

// ---------------------------------------------------------------------------
// Kernel E: pruned irfft along W + residual. x[w] = Re sum_{k<91} g_k X[k]
// e^{+2pi i k w/360}, g_0=1, g_k=2 (hermitian fold). k = k1 + 20*k2 (k2<5),
// w = wm + 18*j. stage1: 5-term register DFT (w18 const). stage2: table
// pre-twiddle + real-output register DFT-20.
// ---------------------------------------------------------------------------
__global__ __launch_bounds__(128) void k_inv_w(const float* __restrict__ xin,
                                               float* __restrict__ outp) {
    __shared__ float2 Xs[RB6][WF + 1];
    __shared__ float2 Ts[18][20][RB6];   // [wm][k1][r]
    __shared__ float  outs[RB6][WW];
    __shared__ float2 tws[360];          // e^{+i theta}
    int tid = threadIdx.x;
    size_t row0 = (size_t)blockIdx.x * RB6;
    const float s = 3.9283710065919305e-3f;   // 1/sqrt(180*360)
    for (int j = tid; j < 360; j += 128) tws[j] = d_tw[j];
    for (int idx = tid; idx < RB6 * WF; idx += 128) {
        int r = idx / WF, k = idx % WF;
        float2 v = d_freq[(row0 + r) * WF + k];
        float g = (k == 0) ? s : 2.f * s;
        Xs[r][k] = make_float2(v.x * g, v.y * g);
    }
    __syncthreads();
    if (tid < 20 * RB6) {
        int k1 = tid % 20, r = tid / 20;
        float2 v[5];
        #pragma unroll
        for (int k2 = 0; k2 < 5; k2++) {
            int k = k1 + 20 * k2;
            v[k2] = (k < WF) ? Xs[r][k] : make_float2(0.f, 0.f);
        }
        #pragma unroll
        for (int wm = 0; wm < 18; wm++) {
            float tr = 0.f, ti = 0.f;
            #pragma unroll
            for (int k2 = 0; k2 < 5; k2++) {
                int m = (k2 * wm) % 18;          // e^{+2pi i k2 wm/18}
                tr += v[k2].x * C18T[m] - v[k2].y * S18T[m];
                ti += v[k2].x * S18T[m] + v[k2].y * C18T[m];
            }
            Ts[wm][k1][r] = make_float2(tr, ti);
        }
    }
    __syncthreads();
    if (tid < 18 * RB6) {
        int wm = tid % 18, r = tid / 18;
        float2 U[20];
        int t = 0;
        #pragma unroll
        for (int k1 = 0; k1 < 20; k1++) {
            float2 a = Ts[wm][k1][r];
            float2 w = tws[t];                   // e^{+2pi i k1 wm/360}
            U[k1] = make_float2(a.x * w.x - a.y * w.y, a.x * w.y + a.y * w.x);
            t += wm; if (t >= 360) t -= 360;
        }
        #pragma unroll
        for (int j = 0; j < 20; j++) {
            float acc = 0.f;
            #pragma unroll
            for (int k1 = 0; k1 < 20; k1++) {
                int m = (k1 * j) % 20;           // Re(U * e^{+2pi i k1 j/20})
                acc += U[k1].x * C20T[m] - U[k1].y * S20T[m];
            }
            outs[r][wm + 18 * j] = acc;
        }
    }
    __syncthreads();
    for (int idx = tid; idx < RB6 * WW; idx += 128)
        outp[row0 * WW + idx] = xin[row0 * WW + idx] + outs[idx / WW][idx % WW];
}

// ---------------------------------------------------------------------------
extern "C" void kernel_launch(void* const* d_in, const int* in_sizes, int n_in,
                              void* d_out, int out_size) {
    const float* x  = (const float*)d_in[0];
    const float* w1 = (const float*)d_in[1];
    const float* b1 = (const float*)d_in[2];
    const float* w2 = (const float*)d_in[3];
    const float* b2 = (const float*)d_in[4];
    float* out = (float*)d_out;

    const float s_fwd = 3.9283710065919305e-3f;  // 1/sqrt(64800), ortho fwd

    k_init_tw<<<3, 128>>>();
    k_fwd_w<<<C_TOT * HH / RB6, 128>>>(x);
    k_fft_h<-1><<<dim3(7, C_TOT), 224>>>(s_fwd);  // forward H FFT + ortho norm
    k_mlp  <<<dim3(NPOS / PT, NBLK), 288>>>(w1, b1, w2, b2);
    k_fft_h< 1><<<dim3(7, C_TOT), 224>>>(1.f);    // inverse H FFT
    k_inv_w<<<C_TOT * HH / RB6, 128>>>(x, out);
}

// round 6
// speedup vs baseline: 2.8877x; 1.3067x over previous
#include <cuda_runtime.h>
#include <cuda_bf16.h>
#include <math.h>
#include <stdint.h>

#define C_TOT 768
#define HH 180
#define WW 360
#define WF 91          // kept modes along W (of 181)
#define NPOS (HH*WF)   // 16380 positions per channel
#define NBLK 8
#define RB6 6          // rows per block in W kernels

// (cos, sin)(2*pi*j/360)
__device__ float2 d_tw[360];
// scratch spectrum, layout [c][kh][wf<91], complex
__device__ float2 d_freq[(size_t)C_TOT * NPOS];
// real-embedded weights, B^T layout [k][n][kk] row-major (192x192 per block)
__device__ uint16_t d_w1b[NBLK * 192 * 192];
__device__ uint16_t d_w2b[NBLK * 192 * 192];

// compile-time root tables
__device__ constexpr float C12T[12] = {1.f, 0.8660254f, 0.5f, 0.f, -0.5f, -0.8660254f,
                            -1.f, -0.8660254f, -0.5f, 0.f, 0.5f, 0.8660254f};
__device__ constexpr float S12T[12] = {0.f, 0.5f, 0.8660254f, 1.f, 0.8660254f, 0.5f,
                            0.f, -0.5f, -0.8660254f, -1.f, -0.8660254f, -0.5f};
__device__ constexpr float C15T[15] = {1.f, 0.91354546f, 0.66913061f, 0.30901699f, -0.10452846f,
                            -0.5f, -0.80901699f, -0.97814760f, -0.97814760f, -0.80901699f,
                            -0.5f, -0.10452846f, 0.30901699f, 0.66913061f, 0.91354546f};
__device__ constexpr float S15T[15] = {0.f, 0.40673664f, 0.74314483f, 0.95105652f, 0.99452190f,
                            0.86602540f, 0.58778525f, 0.20791169f, -0.20791169f, -0.58778525f,
                            -0.86602540f, -0.99452190f, -0.95105652f, -0.74314483f, -0.40673664f};
__device__ constexpr float C18T[18] = {1.f, 0.93969262f, 0.76604444f, 0.5f, 0.17364818f, -0.17364818f,
                            -0.5f, -0.76604444f, -0.93969262f, -1.f, -0.93969262f, -0.76604444f,
                            -0.5f, -0.17364818f, 0.17364818f, 0.5f, 0.76604444f, 0.93969262f};
__device__ constexpr float S18T[18] = {0.f, 0.34202014f, 0.64278761f, 0.86602540f, 0.98480775f, 0.98480775f,
                            0.86602540f, 0.64278761f, 0.34202014f, 0.f, -0.34202014f, -0.64278761f,
                            -0.86602540f, -0.98480775f, -0.98480775f, -0.86602540f, -0.64278761f, -0.34202014f};
__device__ constexpr float C20T[20] = {1.f, 0.95105652f, 0.80901699f, 0.58778525f, 0.30901699f, 0.f,
                            -0.30901699f, -0.58778525f, -0.80901699f, -0.95105652f, -1.f,
                            -0.95105652f, -0.80901699f, -0.58778525f, -0.30901699f, 0.f,
                            0.30901699f, 0.58778525f, 0.80901699f, 0.95105652f};
__device__ constexpr float S20T[20] = {0.f, 0.30901699f, 0.58778525f, 0.80901699f, 0.95105652f, 1.f,
                            0.95105652f, 0.80901699f, 0.58778525f, 0.30901699f, 0.f,
                            -0.30901699f, -0.58778525f, -0.80901699f, -0.95105652f, -1.f,
                            -0.95105652f, -0.80901699f, -0.58778525f, -0.30901699f};

__global__ void k_init_tw() {
    int j = blockIdx.x * blockDim.x + threadIdx.x;
    if (j < 360) {
        double a = (2.0 * 3.14159265358979323846 / 360.0) * (double)j;
        d_tw[j] = make_float2((float)cos(a), (float)sin(a));
    }
}

// Prep: pack complex weights into real-embedded B^T matrices WT[n][kk]:
// WT[2o][2i]=wr, WT[2o][2i+1]=-wi, WT[2o+1][2i]=wi, WT[2o+1][2i+1]=wr
__global__ void k_prep_w(const float* __restrict__ w1, const float* __restrict__ w2) {
    int k = blockIdx.x;
    uint16_t* o1 = d_w1b + (size_t)k * 192 * 192;
    uint16_t* o2 = d_w2b + (size_t)k * 192 * 192;
    for (int idx = threadIdx.x; idx < 96 * 96; idx += blockDim.x) {
        int i = idx / 96, o = idx % 96;
        #pragma unroll
        for (int L = 0; L < 2; L++) {
            const float* w = (L == 0) ? w1 : w2;
            uint16_t* dst  = (L == 0) ? o1 : o2;
            float wr = w[((k * 96 + i) * 96 + o) * 2 + 0];
            float wi = w[((k * 96 + i) * 96 + o) * 2 + 1];
            dst[(2*o)   * 192 + 2*i]     = __bfloat16_as_ushort(__float2bfloat16( wr));
            dst[(2*o)   * 192 + 2*i + 1] = __bfloat16_as_ushort(__float2bfloat16(-wi));
            dst[(2*o+1) * 192 + 2*i]     = __bfloat16_as_ushort(__float2bfloat16( wi));
            dst[(2*o+1) * 192 + 2*i + 1] = __bfloat16_as_ushort(__float2bfloat16( wr));
        }
    }
}

// ========================= mma.sync helpers ================================
__device__ __forceinline__ uint32_t smem_u32(const void* p) {
    uint32_t a;
    asm("{ .reg .u64 t; cvta.to.shared.u64 t, %1; cvt.u32.u64 %0, t; }" : "=r"(a) : "l"(p));
    return a;
}
#define LDSM_X4(r0, r1, r2, r3, addr) \
    asm volatile("ldmatrix.sync.aligned.m8n8.x4.shared.b16 {%0,%1,%2,%3}, [%4];" \
        : "=r"(r0), "=r"(r1), "=r"(r2), "=r"(r3) : "r"(addr))
#define MMA16816(c, a0, a1, a2, a3, b0, b1) \
    asm volatile("mma.sync.aligned.m16n8k16.row.col.f32.bf16.bf16.f32 " \
        "{%0,%1,%2,%3}, {%4,%5,%6,%7}, {%8,%9}, {%0,%1,%2,%3};" \
        : "+f"((c)[0]), "+f"((c)[1]), "+f"((c)[2]), "+f"((c)[3]) \
        : "r"(a0), "r"(a1), "r"(a2), "r"(a3), "r"(b0), "r"(b1))

// ---------------------------------------------------------------------------
// Tensor-core MLP via ldmatrix + mma.sync (baseline PTX, runs on HMMA pipe).
// CTA = (position tile of 128, channel block k). 512 thr = 16 warps:
// warp = (mw = M-tile of 16, nw = N-half of 96). In-place on d_freq.
// smem: A[128][200]bf16 @0 (51200), W[192][200]bf16 @51200 (76800),
//       O1[128][200]bf16 @128000 (51200). Out staging [96][130]f2 @0.
// ---------------------------------------------------------------------------
#define SA   200
#define OFF_A  0
#define OFF_W  51200
#define OFF_O1 128000
#define MLP_SMEM 179200

__global__ void __launch_bounds__(512, 1) k_mlp_mma(const float* __restrict__ b1,
                                                    const float* __restrict__ b2) {
    extern __shared__ char smem[];
    uint32_t sb = smem_u32(smem);
    int tid = threadIdx.x;
    int w   = tid >> 5, l = tid & 31;
    int mw  = w & 7, nw = w >> 3;
    int m0  = mw * 16;
    int k   = blockIdx.y;
    int p0  = blockIdx.x * 128;
    int nv  = NPOS - p0; if (nv > 128) nv = 128;

    // ---- load W1 (rows 192 x 384B, pad to 400B stride) + A tile ----
    {
        const uint4* src = (const uint4*)(d_w1b + (size_t)k * 192 * 192);
        for (int idx = tid; idx < 192 * 24; idx += 512) {
            int r = idx / 24, cc = idx % 24;
            *(uint4*)(smem + OFF_W + r * 400 + cc * 16) = src[r * 24 + cc];
        }
        uint16_t* A = (uint16_t*)(smem + OFF_A);
        for (int idx = tid; idx < 96 * 128; idx += 512) {
            int i = idx >> 7, p = idx & 127;
            float2 v = (p < nv) ? d_freq[(size_t)(k * 96 + i) * NPOS + p0 + p]
                                : make_float2(0.f, 0.f);
            uint32_t u;
            asm("cvt.rn.bf16x2.f32 %0, %1, %2;" : "=r"(u) : "f"(v.y), "f"(v.x));
            *(uint32_t*)&A[p * SA + 2 * i] = u;
        }
    }
    __syncthreads();

    // fragment addresses (bytes)
    uint32_t aRow = (uint32_t)(m0 + (l & 15));
    uint32_t aOff = (l >> 4) * 8;
    uint32_t wRowB = (uint32_t)(nw * 96 + (l & 15));

    float c[12][4];
    // ---- GEMM1: O1 = relu(A x W1 + b1) ----
    {
        const float2* B1 = (const float2*)b1 + k * 96;
        #pragma unroll
        for (int a = 0; a < 12; a++) {
            int o = nw * 48 + a * 4 + (l & 3);
            float2 bb = __ldg(&B1[o]);
            c[a][0] = bb.x; c[a][1] = bb.y; c[a][2] = bb.x; c[a][3] = bb.y;
        }
        #pragma unroll
        for (int kk = 0; kk < 12; kk++) {
            int k0 = kk * 16;
            uint32_t a0, a1, a2, a3;
            LDSM_X4(a0, a1, a2, a3, sb + OFF_A + (aRow * SA + k0 + aOff) * 2);
            #pragma unroll
            for (int g = 0; g < 6; g++) {
                uint32_t b0, b1r, b2, b3;
                LDSM_X4(b0, b1r, b2, b3,
                        sb + OFF_W + ((wRowB + g * 16) * SA + k0 + aOff) * 2);
                MMA16816(c[2 * g],     a0, a1, a2, a3, b0,  b2);
                MMA16816(c[2 * g + 1], a0, a1, a2, a3, b1r, b3);
            }
        }
        // epilogue: relu -> O1 bf16
        uint16_t* O1 = (uint16_t*)(smem + OFF_O1);
        int p1 = m0 + (l >> 2), p2 = p1 + 8;
        #pragma unroll
        for (int a = 0; a < 12; a++) {
            int n = nw * 96 + a * 8 + (l & 3) * 2;
            uint32_t u;
            float r0 = fmaxf(c[a][0], 0.f), i0 = fmaxf(c[a][1], 0.f);
            float r1 = fmaxf(c[a][2], 0.f), i1 = fmaxf(c[a][3], 0.f);
            asm("cvt.rn.bf16x2.f32 %0, %1, %2;" : "=r"(u) : "f"(i0), "f"(r0));
            *(uint32_t*)&O1[p1 * SA + n] = u;
            asm("cvt.rn.bf16x2.f32 %0, %1, %2;" : "=r"(u) : "f"(i1), "f"(r1));
            *(uint32_t*)&O1[p2 * SA + n] = u;
        }
    }
    __syncthreads();
    // ---- load W2 over W1 ----
    {
        const uint4* src = (const uint4*)(d_w2b + (size_t)k * 192 * 192);
        for (int idx = tid; idx < 192 * 24; idx += 512) {
            int r = idx / 24, cc = idx % 24;
            *(uint4*)(smem + OFF_W + r * 400 + cc * 16) = src[r * 24 + cc];
        }
    }
    __syncthreads();

    // ---- GEMM2: out = softshrink(O1 x W2 + b2) ----
    {
        const float2* B2 = (const float2*)b2 + k * 96;
        #pragma unroll
        for (int a = 0; a < 12; a++) {
            int o = nw * 48 + a * 4 + (l & 3);
            float2 bb = __ldg(&B2[o]);
            c[a][0] = bb.x; c[a][1] = bb.y; c[a][2] = bb.x; c[a][3] = bb.y;
        }
        #pragma unroll
        for (int kk = 0; kk < 12; kk++) {
            int k0 = kk * 16;
            uint32_t a0, a1, a2, a3;
            LDSM_X4(a0, a1, a2, a3, sb + OFF_O1 + (aRow * SA + k0 + aOff) * 2);
            #pragma unroll
            for (int g = 0; g < 6; g++) {
                uint32_t b0, b1r, b2, b3;
                LDSM_X4(b0, b1r, b2, b3,
                        sb + OFF_W + ((wRowB + g * 16) * SA + k0 + aOff) * 2);
                MMA16816(c[2 * g],     a0, a1, a2, a3, b0,  b2);
                MMA16816(c[2 * g + 1], a0, a1, a2, a3, b1r, b3);
            }
        }
    }
    __syncthreads();
    // epilogue 2: softshrink -> staging [o][130] float2 at smem base
    {
        float2* outs = (float2*)smem;
        int p1 = m0 + (l >> 2), p2 = p1 + 8;
        #pragma unroll
        for (int a = 0; a < 12; a++) {
            int o = nw * 48 + a * 4 + (l & 3);
            float re = c[a][0], im = c[a][1];
            float vr = fabsf(re) - 0.01f, vi = fabsf(im) - 0.01f;
            re = vr > 0.f ? copysignf(vr, re) : 0.f;
            im = vi > 0.f ? copysignf(vi, im) : 0.f;
            outs[o * 130 + p1] = make_float2(re, im);
            re = c[a][2]; im = c[a][3];
            vr = fabsf(re) - 0.01f; vi = fabsf(im) - 0.01f;
            re = vr > 0.f ? copysignf(vr, re) : 0.f;
            im = vi > 0.f ? copysignf(vi, im) : 0.f;
            outs[o * 130 + p2] = make_float2(re, im);
        }
    }
    __syncthreads();
    {
        const float2* outs = (const float2*)smem;
        for (int idx = tid; idx < 96 * 128; idx += 512) {
            int o = idx >> 7, p = idx & 127;
            if (p < nv)
                d_freq[(size_t)(k * 96 + o) * NPOS + p0 + p] = outs[o * 130 + p];
        }
    }
}

// ---------------------------------------------------------------------------
// Kernel A: rfft along W. 360 = 18*20. (unchanged)
// ---------------------------------------------------------------------------
__global__ __launch_bounds__(128) void k_fwd_w(const float* __restrict__ x) {
    __shared__ float  xs[RB6][WW];
    __shared__ float2 As[20][18][RB6];
    __shared__ float2 tws[360];
    int tid = threadIdx.x;
    size_t row0 = (size_t)blockIdx.x * RB6;
    for (int j = tid; j < 360; j += 128) {
        float2 w = d_tw[j];
        tws[j] = make_float2(w.x, -w.y);
    }
    for (int idx = tid; idx < RB6 * WW; idx += 128)
        xs[idx / WW][idx % WW] = x[row0 * WW + idx];
    __syncthreads();
    if (tid < 18 * RB6) {
        int n2 = tid % 18, r = tid / 18;
        float v[20];
        #pragma unroll
        for (int n1 = 0; n1 < 20; n1++) v[n1] = xs[r][18 * n1 + n2];
        #pragma unroll
        for (int km = 0; km <= 10; km++) {
            float re = 0.f, im = 0.f;
            #pragma unroll
            for (int n1 = 0; n1 < 20; n1++) {
                int m = (n1 * km) % 20;
                re += v[n1] * C20T[m];
                im -= v[n1] * S20T[m];
            }
            As[km][n2][r] = make_float2(re, im);
            if (km >= 1 && km <= 9) As[20 - km][n2][r] = make_float2(re, -im);
        }
    }
    __syncthreads();
    if (tid < 20 * RB6) {
        int km = tid % 20, r = tid / 20;
        float2 B[18];
        int t = 0;
        #pragma unroll
        for (int n2 = 0; n2 < 18; n2++) {
            float2 a = As[km][n2][r];
            float2 w = tws[t];
            B[n2] = make_float2(a.x * w.x - a.y * w.y, a.x * w.y + a.y * w.x);
            t += km; if (t >= 360) t -= 360;
        }
        float2* orow = d_freq + (row0 + r) * WF;
        #pragma unroll
        for (int k2 = 0; k2 < 5; k2++) {
            int k = km + 20 * k2;
            if (k < WF) {
                float xr = 0.f, xi = 0.f;
                #pragma unroll
                for (int n2 = 0; n2 < 18; n2++) {
                    int m = (n2 * k2) % 18;
                    xr += B[n2].x * C18T[m] + B[n2].y * S18T[m];
                    xi += B[n2].y * C18T[m] - B[n2].x * S18T[m];
                }
                orow[k] = make_float2(xr, xi);
            }
        }
    }
}

// ---------------------------------------------------------------------------
// Kernel B/D: complex FFT length 180 along kh (unchanged)
// ---------------------------------------------------------------------------
template <int SGN>
__global__ __launch_bounds__(224) void k_fft_h(float scale) {
    __shared__ float2 in_s[13][HH];
    __shared__ float2 As[13][12][15];
    __shared__ float2 tws[360];
    int tid = threadIdx.x;
    int c   = blockIdx.y;
    int wf0 = blockIdx.x * 13;
    float2* base = d_freq + (size_t)c * NPOS;
    for (int j = tid; j < 360; j += 224) {
        float2 w = d_tw[j];
        tws[j] = make_float2(w.x, SGN < 0 ? -w.y : w.y);
    }
    for (int idx = tid; idx < HH * 13; idx += 224) {
        int kh = idx / 13, col = idx % 13;
        in_s[col][kh] = base[(size_t)kh * WF + wf0 + col];
    }
    __syncthreads();
    if (tid < 15 * 13) {
        int n2 = tid % 15, col = tid / 15;
        float2 v[12];
        #pragma unroll
        for (int n1 = 0; n1 < 12; n1++) v[n1] = in_s[col][15 * n1 + n2];
        #pragma unroll
        for (int km = 0; km < 12; km++) {
            float ar = 0.f, ai = 0.f;
            #pragma unroll
            for (int n1 = 0; n1 < 12; n1++) {
                int m = (n1 * km) % 12;
                float cc = C12T[m];
                float ss = (SGN < 0) ? -S12T[m] : S12T[m];
                ar += v[n1].x * cc - v[n1].y * ss;
                ai += v[n1].x * ss + v[n1].y * cc;
            }
            As[col][km][n2] = make_float2(ar, ai);
        }
    }
    __syncthreads();
    if (tid < 12 * 13) {
        int km = tid % 12, col = tid / 12;
        float2 B[15];
        int t = 0, step = 2 * km;
        #pragma unroll
        for (int n2 = 0; n2 < 15; n2++) {
            float2 a = As[col][km][n2];
            float2 w = tws[t];
            B[n2] = make_float2(a.x * w.x - a.y * w.y, a.x * w.y + a.y * w.x);
            t += step; if (t >= 360) t -= 360;
        }
        #pragma unroll
        for (int k2 = 0; k2 < 15; k2++) {
            float xr = 0.f, xi = 0.f;
            #pragma unroll
            for (int n2 = 0; n2 < 15; n2++) {
                int m = (n2 * k2) % 15;
                float cc = C15T[m];
                float ss = (SGN < 0) ? -S15T[m] : S15T[m];
                xr += B[n2].x * cc - B[n2].y * ss;
                xi += B[n2].x * ss + B[n2].y * cc;
            }
            in_s[col][km + 12 * k2] = make_float2(xr, xi);
        }
    }
    __syncthreads();
    for (int idx = tid; idx < HH * 13; idx += 224) {
        int k = idx / 13, col = idx % 13;
        float2 v = in_s[col][k];
        base[(size_t)k * WF + wf0 + col] = make_float2(v.x * scale, v.y * scale);
    }
}

// ---------------------------------------------------------------------------
// Kernel E: pruned irfft along W + residual (unchanged)
// ---------------------------------------------------------------------------
__global__ __launch_bounds__(128) void k_inv_w(const float* __restrict__ xin,
                                               float* __restrict__ outp) {
    __shared__ float2 Xs[RB6][WF + 1];
    __shared__ float2 Ts[18][20][RB6];
    __shared__ float  outs[RB6][WW];
    __shared__ float2 tws[360];
    int tid = threadIdx.x;
    size_t row0 = (size_t)blockIdx.x * RB6;
    const float s = 3.9283710065919305e-3f;
    for (int j = tid; j < 360; j += 128) tws[j] = d_tw[j];
    for (int idx = tid; idx < RB6 * WF; idx += 128) {
        int r = idx / WF, k = idx % WF;
        float2 v = d_freq[(row0 + r) * WF + k];
        float g = (k == 0) ? s : 2.f * s;
        Xs[r][k] = make_float2(v.x * g, v.y * g);
    }
    __syncthreads();
    if (tid < 20 * RB6) {
        int k1 = tid % 20, r = tid / 20;
        float2 v[5];
        #pragma unroll
        for (int k2 = 0; k2 < 5; k2++) {
            int k = k1 + 20 * k2;
            v[k2] = (k < WF) ? Xs[r][k] : make_float2(0.f, 0.f);
        }
        #pragma unroll
        for (int wm = 0; wm < 18; wm++) {
            float tr = 0.f, ti = 0.f;
            #pragma unroll
            for (int k2 = 0; k2 < 5; k2++) {
                int m = (k2 * wm) % 18;
                tr += v[k2].x * C18T[m] - v[k2].y * S18T[m];
                ti += v[k2].x * S18T[m] + v[k2].y * C18T[m];
            }
            Ts[wm][k1][r] = make_float2(tr, ti);
        }
    }
    __syncthreads();
    if (tid < 18 * RB6) {
        int wm = tid % 18, r = tid / 18;
        float2 U[20];
        int t = 0;
        #pragma unroll
        for (int k1 = 0; k1 < 20; k1++) {
            float2 a = Ts[wm][k1][r];
            float2 w = tws[t];
            U[k1] = make_float2(a.x * w.x - a.y * w.y, a.x * w.y + a.y * w.x);
            t += wm; if (t >= 360) t -= 360;
        }
        #pragma unroll
        for (int j = 0; j < 20; j++) {
            float acc = 0.f;
            #pragma unroll
            for (int k1 = 0; k1 < 20; k1++) {
                int m = (k1 * j) % 20;
                acc += U[k1].x * C20T[m] - U[k1].y * S20T[m];
            }
            outs[r][wm + 18 * j] = acc;
        }
    }
    __syncthreads();
    for (int idx = tid; idx < RB6 * WW; idx += 128)
        outp[row0 * WW + idx] = xin[row0 * WW + idx] + outs[idx / WW][idx % WW];
}

// ---------------------------------------------------------------------------
extern "C" void kernel_launch(void* const* d_in, const int* in_sizes, int n_in,
                              void* d_out, int out_size) {
    const float* x  = (const float*)d_in[0];
    const float* w1 = (const float*)d_in[1];
    const float* b1 = (const float*)d_in[2];
    const float* w2 = (const float*)d_in[3];
    const float* b2 = (const float*)d_in[4];
    float* out = (float*)d_out;

    const float s_fwd = 3.9283710065919305e-3f;  // 1/sqrt(64800), ortho fwd

    cudaFuncSetAttribute(k_mlp_mma, cudaFuncAttributeMaxDynamicSharedMemorySize, MLP_SMEM);

    k_init_tw<<<3, 128>>>();
    k_prep_w<<<NBLK, 256>>>(w1, w2);
    k_fwd_w<<<C_TOT * HH / RB6, 128>>>(x);
    k_fft_h<-1><<<dim3(7, C_TOT), 224>>>(s_fwd);  // forward H FFT + ortho norm
    k_mlp_mma<<<dim3(128, NBLK), 512, MLP_SMEM>>>(b1, b2);
    k_fft_h< 1><<<dim3(7, C_TOT), 224>>>(1.f);    // inverse H FFT
    k_inv_w<<<C_TOT * HH / RB6, 128>>>(x, out);
}